// round 14
// baseline (speedup 1.0000x reference)
#include <cuda_runtime.h>

// Tricubic B-spline, n_ctrl=32, p=3, open-uniform knots.
// zero -> bucket queries by cell (bx,by,bz) into 8 REPLICATED buckets per
// cell (replica = query_idx & 7; kills L2 atomic same-address contention) ->
// eval: each warp processes whole cells, all lanes share every slab address
// -> smem BROADCAST loads. Warp-uniform polynomial basis for interior spans.
// Overflow-safe tail kernel covers replica-bucket overflow.

#define NCTRL   32
#define NCELLS  (29 * 29 * 29)     // 24389
#define NREP    8
#define CAP_R   24
#define OVF_CAP 65536
#define EVAL_THREADS 512
#define MAX_SLAB_BYTES (11 * NCTRL * NCTRL * 16)   // 180224 B

__device__ int    g_cnt[NREP * NCELLS];
__device__ int    g_ovf_cnt;
__device__ float4 g_cell[(size_t)NREP * NCELLS * CAP_R];   // ~75 MB scratch
__device__ float4 g_ovf[OVF_CAP];

// ---------- packed f32x2 helpers ----------
__device__ __forceinline__ unsigned long long f2pack(float a, float b) {
    unsigned long long r;
    asm("mov.b64 %0, {%1, %2};" : "=l"(r) : "f"(a), "f"(b));
    return r;
}
__device__ __forceinline__ void f2unpack(unsigned long long v, float& a, float& b) {
    asm("mov.b64 {%0, %1}, %2;" : "=f"(a), "=f"(b) : "l"(v));
}
__device__ __forceinline__ unsigned long long fma2(
    unsigned long long a, unsigned long long b, unsigned long long c) {
    unsigned long long d;
    asm("fma.rn.f32x2 %0, %1, %2, %3;" : "=l"(d) : "l"(a), "l"(b), "l"(c));
    return d;
}
__device__ __forceinline__ unsigned long long mul2(
    unsigned long long a, unsigned long long b) {
    unsigned long long d;
    asm("mul.rn.f32x2 %0, %1, %2;" : "=l"(d) : "l"(a), "l"(b));
    return d;
}

// ---------- spline primitives ----------
__device__ __forceinline__ int find_span(float u) {
    int s = 3 + (int)floorf(u * 29.0f);
    return min(max(s, 3), NCTRL - 1);
}
__device__ __forceinline__ float knot_val(int k) {
    return __saturatef((float)(k - 3) * (1.0f / 29.0f));
}
// Cox-de Boor (A2.2), p=3 (boundary spans).
__device__ __forceinline__ void basis4(float u, int s, float N[4]) {
    float left[4], right[4];
    N[0] = 1.0f;
#pragma unroll
    for (int j = 1; j <= 3; j++) {
        left[j]  = u - knot_val(s + 1 - j);
        right[j] = knot_val(s + j) - u;
        float saved = 0.0f;
#pragma unroll
        for (int r = 0; r < j; r++) {
            float temp = __fdividef(N[r], right[r + 1] + left[j - r]);
            N[r] = fmaf(right[r + 1], temp, saved);
            saved = left[j - r] * temp;
        }
        N[j] = saved;
    }
}
// Interior spans s in [5,29]: local knots are uniform (h=1/29) -> classic
// uniform cubic B-spline polynomials in t = frac(29u). Warp-uniform branch.
__device__ __forceinline__ void basis_axis(float u, int s, float N[4]) {
    if (s >= 5 && s <= 29) {
        const float c6 = 1.0f / 6.0f;
        float t = fmaf(u, 29.0f, (float)(3 - s));   // in [0,1)
        float omt = 1.0f - t;
        float t2 = t * t, t3 = t2 * t;
        N[0] = c6 * omt * omt * omt;
        N[1] = c6 * fmaf(3.0f, t3, fmaf(-6.0f, t2, 4.0f));
        N[2] = c6 * fmaf(-3.0f, t3, fmaf(3.0f, t2, fmaf(3.0f, t, 1.0f)));
        N[3] = c6 * t3;
    } else {
        basis4(u, s, N);
    }
}

__global__ void zero_kernel() {
    int i = blockIdx.x * blockDim.x + threadIdx.x;
    if (i < NREP * NCELLS) g_cnt[i] = 0;
    if (i == 0) g_ovf_cnt = 0;
}

__global__ void __launch_bounds__(512) compact_kernel(
    const float* __restrict__ q, int Q)
{
    int i = blockIdx.x * blockDim.x + threadIdx.x;
    if (i >= Q) return;
    float ux = q[3 * i], uy = q[3 * i + 1], uz = q[3 * i + 2];
    int bx = find_span(ux) - 3;
    int by = find_span(uy) - 3;
    int bz = find_span(uz) - 3;
    int cell = bx + 29 * (by + 29 * bz);
    int slot = (i & (NREP - 1)) * NCELLS + cell;
    int pos = atomicAdd(&g_cnt[slot], 1);
    float4 e = make_float4(ux, uy, uz, __int_as_float(i));
    if (pos < CAP_R) {
        g_cell[(size_t)slot * CAP_R + pos] = e;
    } else {
        int o = atomicAdd(&g_ovf_cnt, 1);
        if (o < OVF_CAP) g_ovf[o] = e;
    }
}

extern __shared__ float4 slab[];

// 148 CTAs, one wave. Bin CTA counts {36,36,35,41} match z-mass 7/7/7/8.
__global__ void __launch_bounds__(EVAL_THREADS) eval_kernel(
    const float* __restrict__ cp, float* __restrict__ out)
{
    const int tid = threadIdx.x;
    int b = blockIdx.x, bin, sub, nctas;
    if (b < 36)       { bin = 0; sub = b;       nctas = 36; }
    else if (b < 72)  { bin = 1; sub = b - 36;  nctas = 36; }
    else if (b < 107) { bin = 2; sub = b - 72;  nctas = 35; }
    else              { bin = 3; sub = b - 107; nctas = 41; }

    const int lo = 7 * bin;
    const int nslices = (bin < 3) ? 10 : 11;
    const int npts = nslices * NCTRL * NCTRL;
    const int gbase = lo * NCTRL * NCTRL;

    for (int idx = tid; idx < npts; idx += EVAL_THREADS) {
        const float* s = cp + 3 * (gbase + idx);
        slab[idx] = make_float4(s[0], s[1], s[2], 0.0f);
    }
    __syncthreads();

    const ulonglong2* __restrict__ slab_u = (const ulonglong2*)slab;

    const int lane = tid & 31, warp = tid >> 5;
    const int cellLo = 5887 * bin;
    const int cellHi = (bin < 3) ? cellLo + 5887 : NCELLS;
    const int gw = sub * (EVAL_THREADS / 32) + warp;
    const int wstep = nctas * (EVAL_THREADS / 32);

    for (int cell = cellLo + gw; cell < cellHi; cell += wstep) {
        int c[NREP];
#pragma unroll
        for (int r = 0; r < NREP; r++)
            c[r] = min(g_cnt[r * NCELLS + cell], CAP_R);
        int p[NREP + 1];
        p[0] = 0;
#pragma unroll
        for (int r = 0; r < NREP; r++) p[r + 1] = p[r] + c[r];
        const int cnt = p[NREP];
        if (cnt == 0) continue;

        const int bx = cell % 29;
        const int by = (cell / 29) % 29;
        const int zslice = cell / 841;
        const int zoff = zslice - lo;
        const int sx = bx + 3, sy = by + 3, sz = zslice + 3;

        for (int c0 = 0; c0 < cnt; c0 += 32) {
            const int rem = cnt - c0;
            const int t = c0 + min(lane, rem - 1);

            int r = 0, pb = 0;
#pragma unroll
            for (int rr = 1; rr < NREP; rr++) {
                bool ge = t >= p[rr];
                r += ge;
                pb = ge ? p[rr] : pb;
            }
            float4 qd =
                g_cell[(size_t)(r * NCELLS + cell) * CAP_R + (t - pb)];

            float Nx[4], Ny[4], Nz[4];
            basis_axis(qd.x, sx, Nx);
            basis_axis(qd.y, sy, Ny);
            basis_axis(qd.z, sz, Nz);

            unsigned long long nx2[4], ny2[4], nz2[4];
#pragma unroll
            for (int tt = 0; tt < 4; tt++) {
                nx2[tt] = f2pack(Nx[tt], Nx[tt]);
                ny2[tt] = f2pack(Ny[tt], Ny[tt]);
                nz2[tt] = f2pack(Nz[tt], Nz[tt]);
            }

            unsigned long long acc01 = 0ull, acc23 = 0ull;
#pragma unroll
            for (int k = 0; k < 4; k++) {
                unsigned long long tk01 = 0ull, tk23 = 0ull;
#pragma unroll
                for (int j = 0; j < 4; j++) {
                    const ulonglong2* ptr =
                        slab_u + bx + NCTRL * ((by + j) + NCTRL * (zoff + k));
                    ulonglong2 c0v = ptr[0], c1v = ptr[1];
                    ulonglong2 c2v = ptr[2], c3v = ptr[3];
                    unsigned long long s01 = mul2(nx2[0], c0v.x);
                    unsigned long long s23 = mul2(nx2[0], c0v.y);
                    s01 = fma2(nx2[1], c1v.x, s01);
                    s23 = fma2(nx2[1], c1v.y, s23);
                    s01 = fma2(nx2[2], c2v.x, s01);
                    s23 = fma2(nx2[2], c2v.y, s23);
                    s01 = fma2(nx2[3], c3v.x, s01);
                    s23 = fma2(nx2[3], c3v.y, s23);
                    if (j == 0) {
                        tk01 = mul2(ny2[0], s01);
                        tk23 = mul2(ny2[0], s23);
                    } else {
                        tk01 = fma2(ny2[j], s01, tk01);
                        tk23 = fma2(ny2[j], s23, tk23);
                    }
                }
                acc01 = fma2(nz2[k], tk01, acc01);
                acc23 = fma2(nz2[k], tk23, acc23);
            }

            if (lane < rem) {
                float ax, ay, az, junk;
                f2unpack(acc01, ax, ay);
                f2unpack(acc23, az, junk);
                int i = __float_as_int(qd.w);
                out[3 * i + 0] = ax;
                out[3 * i + 1] = ay;
                out[3 * i + 2] = az;
            }
        }
    }
}

// Tail: replica-bucket overflow entries via direct global gather.
__global__ void __launch_bounds__(256) ovf_kernel(
    const float* __restrict__ cp, float* __restrict__ out)
{
    int n = min(g_ovf_cnt, OVF_CAP);
    for (int t = blockIdx.x * blockDim.x + threadIdx.x; t < n;
         t += gridDim.x * blockDim.x) {
        float4 qd = g_ovf[t];
        int sx = find_span(qd.x), sy = find_span(qd.y), sz = find_span(qd.z);
        float Nx[4], Ny[4], Nz[4];
        basis4(qd.x, sx, Nx); basis4(qd.y, sy, Ny); basis4(qd.z, sz, Nz);
        int bx = sx - 3, by = sy - 3, bz = sz - 3;
        float ax = 0, ay = 0, az = 0;
#pragma unroll
        for (int k = 0; k < 4; k++)
#pragma unroll
            for (int j = 0; j < 4; j++) {
                float w = Nz[k] * Ny[j];
                const float* p =
                    cp + 3 * (bx + NCTRL * ((by + j) + NCTRL * (bz + k)));
#pragma unroll
                for (int ii = 0; ii < 4; ii++) {
                    float wv = w * Nx[ii];
                    ax = fmaf(wv, __ldg(p + 3 * ii + 0), ax);
                    ay = fmaf(wv, __ldg(p + 3 * ii + 1), ay);
                    az = fmaf(wv, __ldg(p + 3 * ii + 2), az);
                }
            }
        int i = __float_as_int(qd.w);
        out[3 * i + 0] = ax; out[3 * i + 1] = ay; out[3 * i + 2] = az;
    }
}

// Fallback for oversized query counts (scratch sizing).
__global__ void __launch_bounds__(256) direct_kernel(
    const float* __restrict__ q, const float* __restrict__ cp,
    float* __restrict__ out, int Q)
{
    int i = blockIdx.x * blockDim.x + threadIdx.x;
    if (i >= Q) return;
    float ux = q[3 * i], uy = q[3 * i + 1], uz = q[3 * i + 2];
    int sx = find_span(ux), sy = find_span(uy), sz = find_span(uz);
    float Nx[4], Ny[4], Nz[4];
    basis4(ux, sx, Nx); basis4(uy, sy, Ny); basis4(uz, sz, Nz);
    int bx = sx - 3, by = sy - 3, bz = sz - 3;
    float ax = 0, ay = 0, az = 0;
#pragma unroll
    for (int k = 0; k < 4; k++)
#pragma unroll
        for (int j = 0; j < 4; j++) {
            float w = Nz[k] * Ny[j];
            const float* p = cp + 3 * (bx + NCTRL * ((by + j) + NCTRL * (bz + k)));
#pragma unroll
            for (int ii = 0; ii < 4; ii++) {
                float wv = w * Nx[ii];
                ax = fmaf(wv, __ldg(p + 3 * ii + 0), ax);
                ay = fmaf(wv, __ldg(p + 3 * ii + 1), ay);
                az = fmaf(wv, __ldg(p + 3 * ii + 2), az);
            }
        }
    out[3 * i + 0] = ax; out[3 * i + 1] = ay; out[3 * i + 2] = az;
}

extern "C" void kernel_launch(void* const* d_in, const int* in_sizes, int n_in,
                              void* d_out, int out_size)
{
    int qi = 0, ci = 1;
    if (n_in >= 2 && in_sizes[1] > in_sizes[0]) { qi = 1; ci = 0; }
    const float* q  = (const float*)d_in[qi];
    const float* cp = (const float*)d_in[ci];
    int Q = in_sizes[qi] / 3;
    if (Q <= 0) return;

    if (Q > 2500000) {
        direct_kernel<<<(Q + 255) / 256, 256>>>(q, cp, (float*)d_out, Q);
        return;
    }

    static int smem_set = 0;
    if (!smem_set) {
        cudaFuncSetAttribute(eval_kernel,
                             cudaFuncAttributeMaxDynamicSharedMemorySize,
                             MAX_SLAB_BYTES);
        smem_set = 1;
    }

    zero_kernel<<<(NREP * NCELLS + 255) / 256, 256>>>();
    compact_kernel<<<(Q + 511) / 512, 512>>>(q, Q);
    eval_kernel<<<148, EVAL_THREADS, MAX_SLAB_BYTES>>>(cp, (float*)d_out);
    ovf_kernel<<<16, 256>>>(cp, (float*)d_out);
}

// round 17
// speedup vs baseline: 4.1572x; 4.1572x over previous
#include <cuda_runtime.h>

// Tricubic B-spline, n_ctrl=32, p=3, open-uniform knots.
// zero -> compact into 80 (z-bin, bx mod 8) lists -> eval: 296 CTAs (2/SM,
// one wave), 96KB slab per CTA, lane l serves bank class l&7 => conflict-free
// LDS.128 broadcast-free gather, packed f32x2 FMA tree.

#define NCTRL   32
#define NZBINS  10
#define NCLASS  8
#define NKEYS   (NZBINS * NCLASS)       // 80
#define STRIDE  36000
#define EVAL_THREADS 320
#define CCHUNK  2048
#define CTHREADS 512
#define MAX_SLAB_BYTES (6 * NCTRL * NCTRL * 16)   // 98304 B

__device__ int    g_cnt[NKEYS];
__device__ float4 g_qlist[(size_t)NKEYS * STRIDE];   // ~46 MB scratch

// ---------- packed f32x2 helpers ----------
__device__ __forceinline__ unsigned long long f2pack(float a, float b) {
    unsigned long long r;
    asm("mov.b64 %0, {%1, %2};" : "=l"(r) : "f"(a), "f"(b));
    return r;
}
__device__ __forceinline__ void f2unpack(unsigned long long v, float& a, float& b) {
    asm("mov.b64 {%0, %1}, %2;" : "=f"(a), "=f"(b) : "l"(v));
}
__device__ __forceinline__ unsigned long long fma2(
    unsigned long long a, unsigned long long b, unsigned long long c) {
    unsigned long long d;
    asm("fma.rn.f32x2 %0, %1, %2, %3;" : "=l"(d) : "l"(a), "l"(b), "l"(c));
    return d;
}
__device__ __forceinline__ unsigned long long mul2(
    unsigned long long a, unsigned long long b) {
    unsigned long long d;
    asm("mul.rn.f32x2 %0, %1, %2;" : "=l"(d) : "l"(a), "l"(b));
    return d;
}

// ---------- spline primitives ----------
__device__ __forceinline__ int find_span(float u) {
    int s = 3 + (int)floorf(u * 29.0f);
    return min(max(s, 3), NCTRL - 1);
}
__device__ __forceinline__ float knot_val(int k) {
    return __saturatef((float)(k - 3) * (1.0f / 29.0f));
}
// Cox-de Boor (A2.2), p=3.
__device__ __forceinline__ void basis4(float u, int s, float N[4]) {
    float left[4], right[4];
    N[0] = 1.0f;
#pragma unroll
    for (int j = 1; j <= 3; j++) {
        left[j]  = u - knot_val(s + 1 - j);
        right[j] = knot_val(s + j) - u;
        float saved = 0.0f;
#pragma unroll
        for (int r = 0; r < j; r++) {
            float temp = __fdividef(N[r], right[r + 1] + left[j - r]);
            N[r] = fmaf(right[r + 1], temp, saved);
            saved = left[j - r] * temp;
        }
        N[j] = saved;
    }
}
// z-bins: bz/3 for bz 0..26 (bins 0..8, width 3), bin 9 = bz {27,28} (width 2)
__device__ __forceinline__ int bin_of(int bz) { return min(bz / 3, NZBINS - 1); }

__global__ void zero_kernel() {
    if (threadIdx.x < NKEYS) g_cnt[threadIdx.x] = 0;
}

__global__ void __launch_bounds__(CTHREADS) compact_kernel(
    const float* __restrict__ q, int Q)
{
    __shared__ float s_q[CCHUNK * 3];
    __shared__ unsigned char s_key[CCHUNK];
    __shared__ int s_cnt[NKEYS], s_base[NKEYS], s_off[NKEYS];
    const unsigned FULL = 0xffffffffu;
    const int tid = threadIdx.x, lane = tid & 31;

    const int start = blockIdx.x * CCHUNK;
    const int n = min(CCHUNK, Q - start);
    if (n <= 0) return;

    if (tid < NKEYS) { s_cnt[tid] = 0; s_off[tid] = 0; }
    __syncthreads();

    for (int t = tid; t < 3 * n; t += CTHREADS) s_q[t] = q[3 * start + t];
    __syncthreads();

    const int padded = ((n + CTHREADS - 1) / CTHREADS) * CTHREADS;

    // pass 1: per-CTA key counts
    for (int k = tid; k < padded; k += CTHREADS) {
        bool valid = k < n;
        int key = 255;
        if (valid) {
            int bx = find_span(s_q[3 * k]) - 3;
            int bz = find_span(s_q[3 * k + 2]) - 3;
            key = bin_of(bz) * NCLASS + (bx & 7);
            s_key[k] = (unsigned char)key;
        }
        unsigned peers = __match_any_sync(FULL, key);
        if (valid && lane == (__ffs(peers) - 1))
            atomicAdd(&s_cnt[key], __popc(peers));
    }
    __syncthreads();

    if (tid < NKEYS) s_base[tid] = atomicAdd(&g_cnt[tid], s_cnt[tid]);
    __syncthreads();

    // pass 2: scatter (ux,uy,uz,idx)
    for (int k = tid; k < padded; k += CTHREADS) {
        bool valid = k < n;
        int key = valid ? (int)s_key[k] : 255;
        unsigned peers = __match_any_sync(FULL, key);
        int leader = __ffs(peers) - 1;
        int rank = __popc(peers & ((1u << lane) - 1));
        int wb = 0;
        if (valid && lane == leader) wb = atomicAdd(&s_off[key], __popc(peers));
        wb = __shfl_sync(FULL, wb, leader);
        if (valid) {
            int pos = s_base[key] + wb + rank;
            if (pos < STRIDE)
                g_qlist[(size_t)key * STRIDE + pos] =
                    make_float4(s_q[3 * k], s_q[3 * k + 1], s_q[3 * k + 2],
                                __int_as_float(start + k));
        }
    }
}

extern __shared__ float4 slab[];

// 296 CTAs = 2/SM, one wave. Bins {30 CTAs x 9, 26 CTAs x 1}.
__global__ void __launch_bounds__(EVAL_THREADS, 2) eval_kernel(
    const float* __restrict__ cp, float* __restrict__ out)
{
    const int tid = threadIdx.x;
    int b = blockIdx.x, bin, sub, nctas;
    if (b < 270) { bin = b / 30; sub = b % 30;  nctas = 30; }
    else         { bin = 9;      sub = b - 270; nctas = 26; }

    const int lo = 3 * bin;                      // first bz of bin
    const int nslices = (bin < 9) ? 6 : 5;       // z-slices lo .. lo+nslices-1
    const int npts = nslices * NCTRL * NCTRL;
    const int gbase = lo * NCTRL * NCTRL;

    for (int idx = tid; idx < npts; idx += EVAL_THREADS) {
        const float* s = cp + 3 * (gbase + idx);
        slab[idx] = make_float4(s[0], s[1], s[2], 0.0f);
    }
    __syncthreads();

    const ulonglong2* __restrict__ slab_u = (const ulonglong2*)slab;

    const int lane = tid & 31, warp = tid >> 5;   // 10 warps
    const int cls = lane & 7;
    const int sub8 = lane >> 3;
    const int key = bin * NCLASS + cls;
    const int cnt = min(g_cnt[key], STRIDE);
    const float4* __restrict__ list = g_qlist + (size_t)key * STRIDE;

    // dummy query: correct bank class + z inside this bin
    const float dux = ((float)cls + 0.5f) * (1.0f / 29.0f);
    const float duz = ((float)lo + 0.5f) * (1.0f / 29.0f);

    int pos = (sub * (EVAL_THREADS / 32) + warp) * 4 + sub8;
    const int step = nctas * (EVAL_THREADS / 32) * 4;

    while (true) {
        bool active = pos < cnt;
        if (!__ballot_sync(0xffffffffu, active)) break;

        float4 qd = active ? list[pos] : make_float4(dux, 0.5f, duz, 0.0f);

        float ux = qd.x, uy = qd.y, uz = qd.z;
        int sx = find_span(ux), sy = find_span(uy), sz = find_span(uz);
        float Nx[4], Ny[4], Nz[4];
        basis4(ux, sx, Nx);
        basis4(uy, sy, Ny);
        basis4(uz, sz, Nz);

        unsigned long long nx2[4], ny2[4], nz2[4];
#pragma unroll
        for (int t = 0; t < 4; t++) {
            nx2[t] = f2pack(Nx[t], Nx[t]);
            ny2[t] = f2pack(Ny[t], Ny[t]);
            nz2[t] = f2pack(Nz[t], Nz[t]);
        }

        const int bx = sx - 3, by = sy - 3, zoff = (sz - 3) - lo;

        unsigned long long acc01 = 0ull, acc23 = 0ull;
#pragma unroll
        for (int k = 0; k < 4; k++) {
            unsigned long long tk01 = 0ull, tk23 = 0ull;
#pragma unroll
            for (int j = 0; j < 4; j++) {
                const ulonglong2* p =
                    slab_u + bx + NCTRL * ((by + j) + NCTRL * (zoff + k));
                ulonglong2 c0 = p[0], c1 = p[1], c2 = p[2], c3 = p[3];
                unsigned long long s01 = mul2(nx2[0], c0.x);
                unsigned long long s23 = mul2(nx2[0], c0.y);
                s01 = fma2(nx2[1], c1.x, s01);
                s23 = fma2(nx2[1], c1.y, s23);
                s01 = fma2(nx2[2], c2.x, s01);
                s23 = fma2(nx2[2], c2.y, s23);
                s01 = fma2(nx2[3], c3.x, s01);
                s23 = fma2(nx2[3], c3.y, s23);
                if (j == 0) {
                    tk01 = mul2(ny2[0], s01);
                    tk23 = mul2(ny2[0], s23);
                } else {
                    tk01 = fma2(ny2[j], s01, tk01);
                    tk23 = fma2(ny2[j], s23, tk23);
                }
            }
            acc01 = fma2(nz2[k], tk01, acc01);
            acc23 = fma2(nz2[k], tk23, acc23);
        }

        if (active) {
            float ax, ay, az, junk;
            f2unpack(acc01, ax, ay);
            f2unpack(acc23, az, junk);
            int i = __float_as_int(qd.w);
            out[3 * i + 0] = ax;
            out[3 * i + 1] = ay;
            out[3 * i + 2] = az;
        }
        pos += step;
    }
}

// Robust fallback for oversized query counts (scratch sizing).
__global__ void __launch_bounds__(256) direct_kernel(
    const float* __restrict__ q, const float* __restrict__ cp,
    float* __restrict__ out, int Q)
{
    int i = blockIdx.x * blockDim.x + threadIdx.x;
    if (i >= Q) return;
    float ux = q[3 * i], uy = q[3 * i + 1], uz = q[3 * i + 2];
    int sx = find_span(ux), sy = find_span(uy), sz = find_span(uz);
    float Nx[4], Ny[4], Nz[4];
    basis4(ux, sx, Nx); basis4(uy, sy, Ny); basis4(uz, sz, Nz);
    int bx = sx - 3, by = sy - 3, bz = sz - 3;
    float ax = 0, ay = 0, az = 0;
#pragma unroll
    for (int k = 0; k < 4; k++)
#pragma unroll
        for (int j = 0; j < 4; j++) {
            float w = Nz[k] * Ny[j];
            const float* p = cp + 3 * (bx + NCTRL * ((by + j) + NCTRL * (bz + k)));
#pragma unroll
            for (int ii = 0; ii < 4; ii++) {
                float wv = w * Nx[ii];
                ax = fmaf(wv, __ldg(p + 3 * ii + 0), ax);
                ay = fmaf(wv, __ldg(p + 3 * ii + 1), ay);
                az = fmaf(wv, __ldg(p + 3 * ii + 2), az);
            }
        }
    out[3 * i + 0] = ax; out[3 * i + 1] = ay; out[3 * i + 2] = az;
}

extern "C" void kernel_launch(void* const* d_in, const int* in_sizes, int n_in,
                              void* d_out, int out_size)
{
    int qi = 0, ci = 1;
    if (n_in >= 2 && in_sizes[1] > in_sizes[0]) { qi = 1; ci = 0; }
    const float* q  = (const float*)d_in[qi];
    const float* cp = (const float*)d_in[ci];
    int Q = in_sizes[qi] / 3;
    if (Q <= 0) return;

    if (Q > 2200000) {   // per-key scratch sizing; take safe path
        direct_kernel<<<(Q + 255) / 256, 256>>>(q, cp, (float*)d_out, Q);
        return;
    }

    static int smem_set = 0;
    if (!smem_set) {
        cudaFuncSetAttribute(eval_kernel,
                             cudaFuncAttributeMaxDynamicSharedMemorySize,
                             MAX_SLAB_BYTES);
        smem_set = 1;
    }

    zero_kernel<<<1, 128>>>();
    compact_kernel<<<(Q + CCHUNK - 1) / CCHUNK, CTHREADS>>>(q, Q);
    eval_kernel<<<296, EVAL_THREADS, MAX_SLAB_BYTES>>>(cp, (float*)d_out);
}